// round 4
// baseline (speedup 1.0000x reference)
#include <cuda_runtime.h>

#define N_NODES_MAX 50000
#define N_EDGES_MAX 800000
#define IN_CH 64
#define HIDDEN 16
#define OUT_CH 8
#define SCAN_THREADS 1024

// Scratch (allocation-free rule: __device__ globals)
__device__ int   g_is64;
__device__ int   g_degi[N_NODES_MAX];   // in-degree (int)
__device__ int   g_off [N_NODES_MAX];   // CSR row offsets (exclusive prefix)
__device__ int   g_cur [N_NODES_MAX];   // build cursors (copy of offsets)
__device__ int   g_csr [N_EDGES_MAX];   // neighbor src ids grouped by dst
__device__ float g_p1[N_NODES_MAX * HIDDEN];
__device__ float g_r1[N_NODES_MAX * HIDDEN];
__device__ float g_p2[N_NODES_MAX * OUT_CH];
__device__ float g_r2[N_NODES_MAX * OUT_CH];

// Decode one edge from raw buffer (int64 or int32 little-endian).
__device__ __forceinline__ void load_edge(const int* __restrict__ ei, int e,
                                          int n_edges, int& src, int& dst) {
    if (g_is64) {
        const int2* p = reinterpret_cast<const int2*>(ei);
        src = p[e].x;
        dst = p[n_edges + e].x;
    } else {
        src = ei[e];
        dst = ei[n_edges + e];
    }
}

// Zero degree counters + dtype detection.
// int64 little-endian with indices in [0,50000): every odd int32 word is 0.
// int32: odd words are random indices — all-zero over 512 samples impossible.
__global__ void init_kernel(const int* __restrict__ ei_raw, int n_words, int n_nodes) {
    int i = blockIdx.x * blockDim.x + threadIdx.x;
    if (i == 0) {
        int nz = 0;
        int lim = n_words < 1024 ? n_words : 1024;
        for (int w = 1; w < lim; w += 2) nz += (ei_raw[w] != 0);
        g_is64 = (nz == 0) ? 1 : 0;
    }
    if (i < n_nodes) g_degi[i] = 0;
}

// Pass 1: in-degree count.
__global__ void count_kernel(const int* __restrict__ ei, int n_edges, int n_nodes) {
    int e = blockIdx.x * blockDim.x + threadIdx.x;
    if (e >= n_edges) return;
    int src, dst;
    load_edge(ei, e, n_edges, src, dst);
    if ((unsigned)src < (unsigned)n_nodes && (unsigned)dst < (unsigned)n_nodes)
        atomicAdd(&g_degi[dst], 1);
}

// Exclusive prefix scan of g_degi -> g_off and g_cur. Single block.
__global__ void scan_kernel(int n_nodes) {
    __shared__ int ssum[SCAN_THREADS];
    int tid = threadIdx.x;
    int chunk = (n_nodes + SCAN_THREADS - 1) / SCAN_THREADS;
    int start = tid * chunk;
    int end = start + chunk;
    if (end > n_nodes) end = n_nodes;

    int s = 0;
    for (int i = start; i < end; i++) s += g_degi[i];
    ssum[tid] = s;
    __syncthreads();
    // Hillis-Steele inclusive scan over block sums
    for (int ofs = 1; ofs < SCAN_THREADS; ofs <<= 1) {
        int v = (tid >= ofs) ? ssum[tid - ofs] : 0;
        __syncthreads();
        ssum[tid] += v;
        __syncthreads();
    }
    int base = (tid == 0) ? 0 : ssum[tid - 1];
    for (int i = start; i < end; i++) {
        g_off[i] = base;
        g_cur[i] = base;
        base += g_degi[i];
    }
}

// Pass 2: place src ids into CSR slots.
__global__ void build_kernel(const int* __restrict__ ei, int n_edges, int n_nodes) {
    int e = blockIdx.x * blockDim.x + threadIdx.x;
    if (e >= n_edges) return;
    int src, dst;
    load_edge(ei, e, n_edges, src, dst);
    if ((unsigned)src < (unsigned)n_nodes && (unsigned)dst < (unsigned)n_nodes) {
        int pos = atomicAdd(&g_cur[dst], 1);
        g_csr[pos] = src;
    }
}

// p1 = x @ W1l^T ; r1 = x @ W1r^T + b1
// 4 threads per node; thread quarter q computes hidden channels [4q, 4q+4).
__global__ void gemm1_kernel(const float* __restrict__ x,
                             const float* __restrict__ W1l,
                             const float* __restrict__ W1r,
                             const float* __restrict__ b1,
                             int n_nodes) {
    __shared__ float sWl[HIDDEN * IN_CH];
    __shared__ float sWr[HIDDEN * IN_CH];
    __shared__ float sb[HIDDEN];
    for (int i = threadIdx.x; i < HIDDEN * IN_CH; i += blockDim.x) {
        sWl[i] = W1l[i];
        sWr[i] = W1r[i];
    }
    if (threadIdx.x < HIDDEN) sb[threadIdx.x] = b1[threadIdx.x];
    __syncthreads();

    int idx = blockIdx.x * blockDim.x + threadIdx.x;
    int n = idx >> 2;
    int q = idx & 3;
    if (n >= n_nodes) return;
    int h0 = q * 4;

    float accl[4], accr[4];
#pragma unroll
    for (int j = 0; j < 4; j++) { accl[j] = 0.0f; accr[j] = sb[h0 + j]; }

    const float4* xr = reinterpret_cast<const float4*>(x + (size_t)n * IN_CH);
#pragma unroll
    for (int c4 = 0; c4 < IN_CH / 4; c4++) {
        float4 v = xr[c4];
#pragma unroll
        for (int j = 0; j < 4; j++) {
            const float* wl = &sWl[(h0 + j) * IN_CH + c4 * 4];
            const float* wr = &sWr[(h0 + j) * IN_CH + c4 * 4];
            accl[j] += v.x * wl[0] + v.y * wl[1] + v.z * wl[2] + v.w * wl[3];
            accr[j] += v.x * wr[0] + v.y * wr[1] + v.z * wr[2] + v.w * wr[3];
        }
    }
    float4* p1o = reinterpret_cast<float4*>(&g_p1[n * HIDDEN + h0]);
    float4* r1o = reinterpret_cast<float4*>(&g_r1[n * HIDDEN + h0]);
    *p1o = make_float4(accl[0], accl[1], accl[2], accl[3]);
    *r1o = make_float4(accr[0], accr[1], accr[2], accr[3]);
}

// Fused: gather-mean over neighbors (layer1) + relu + layer-2 projection.
// 4 threads per node (quad); each gathers a float4 channel slice, then a
// butterfly shuffle across the quad reduces the layer-2 partial products.
__global__ void gather1_layer2_kernel(const float* __restrict__ W2l,
                                      const float* __restrict__ W2r,
                                      const float* __restrict__ b2,
                                      int n_nodes) {
    __shared__ float sWl[OUT_CH * HIDDEN];
    __shared__ float sWr[OUT_CH * HIDDEN];
    __shared__ float sb[OUT_CH];
    for (int i = threadIdx.x; i < OUT_CH * HIDDEN; i += blockDim.x) {
        sWl[i] = W2l[i];
        sWr[i] = W2r[i];
    }
    if (threadIdx.x < OUT_CH) sb[threadIdx.x] = b2[threadIdx.x];
    __syncthreads();

    int idx = blockIdx.x * blockDim.x + threadIdx.x;
    int n = idx >> 2;
    int q = idx & 3;
    bool valid = (n < n_nodes);
    if (n >= n_nodes) n = n_nodes - 1;   // clamp; keep quad converged for shfl

    int off = g_off[n];
    int deg = g_degi[n];
    int end = off + deg;

    float4 sum = make_float4(0.f, 0.f, 0.f, 0.f);
    int j = off;
    for (; j + 4 <= end; j += 4) {
        int s0 = g_csr[j + 0];
        int s1 = g_csr[j + 1];
        int s2 = g_csr[j + 2];
        int s3 = g_csr[j + 3];
        float4 v0 = *reinterpret_cast<const float4*>(&g_p1[s0 * HIDDEN + q * 4]);
        float4 v1 = *reinterpret_cast<const float4*>(&g_p1[s1 * HIDDEN + q * 4]);
        float4 v2 = *reinterpret_cast<const float4*>(&g_p1[s2 * HIDDEN + q * 4]);
        float4 v3 = *reinterpret_cast<const float4*>(&g_p1[s3 * HIDDEN + q * 4]);
        sum.x += v0.x + v1.x + v2.x + v3.x;
        sum.y += v0.y + v1.y + v2.y + v3.y;
        sum.z += v0.z + v1.z + v2.z + v3.z;
        sum.w += v0.w + v1.w + v2.w + v3.w;
    }
    for (; j < end; j++) {
        int s = g_csr[j];
        float4 v = *reinterpret_cast<const float4*>(&g_p1[s * HIDDEN + q * 4]);
        sum.x += v.x; sum.y += v.y; sum.z += v.z; sum.w += v.w;
    }

    float inv_d = 1.0f / fmaxf((float)deg, 1.0f);
    float4 r = *reinterpret_cast<const float4*>(&g_r1[n * HIDDEN + q * 4]);
    float h[4];
    h[0] = fmaxf(sum.x * inv_d + r.x, 0.0f);
    h[1] = fmaxf(sum.y * inv_d + r.y, 0.0f);
    h[2] = fmaxf(sum.z * inv_d + r.z, 0.0f);
    h[3] = fmaxf(sum.w * inv_d + r.w, 0.0f);

    // Partial layer-2 products over this thread's 4 channels.
    float acc[2 * OUT_CH];
#pragma unroll
    for (int o = 0; o < OUT_CH; o++) {
        float al = 0.f, ar = 0.f;
#pragma unroll
        for (int k = 0; k < 4; k++) {
            al += h[k] * sWl[o * HIDDEN + q * 4 + k];
            ar += h[k] * sWr[o * HIDDEN + q * 4 + k];
        }
        acc[o] = al;
        acc[OUT_CH + o] = ar;
    }
    // Butterfly reduce across the quad (lanes differ in bits 0,1).
    unsigned mask = __activemask();
#pragma unroll
    for (int m = 1; m <= 2; m <<= 1) {
#pragma unroll
        for (int t = 0; t < 2 * OUT_CH; t++)
            acc[t] += __shfl_xor_sync(mask, acc[t], m);
    }
    if (valid) {
        // thread q writes outputs {2q, 2q+1}
        float2 pl = make_float2(acc[2 * q], acc[2 * q + 1]);
        float2 pr = make_float2(acc[OUT_CH + 2 * q] + sb[2 * q],
                                acc[OUT_CH + 2 * q + 1] + sb[2 * q + 1]);
        *reinterpret_cast<float2*>(&g_p2[n * OUT_CH + 2 * q]) = pl;
        *reinterpret_cast<float2*>(&g_r2[n * OUT_CH + 2 * q]) = pr;
    }
}

// Fused: gather-mean over neighbors (layer2) + final combine -> d_out.
// 2 threads per node, each owns a float4 slice of the 8 output channels.
__global__ void gather2_combine_kernel(float* __restrict__ out, int n_nodes) {
    int idx = blockIdx.x * blockDim.x + threadIdx.x;
    int n = idx >> 1;
    int q = idx & 1;
    if (n >= n_nodes) return;

    int off = g_off[n];
    int deg = g_degi[n];
    int end = off + deg;

    float4 sum = make_float4(0.f, 0.f, 0.f, 0.f);
    int j = off;
    for (; j + 4 <= end; j += 4) {
        int s0 = g_csr[j + 0];
        int s1 = g_csr[j + 1];
        int s2 = g_csr[j + 2];
        int s3 = g_csr[j + 3];
        float4 v0 = *reinterpret_cast<const float4*>(&g_p2[s0 * OUT_CH + q * 4]);
        float4 v1 = *reinterpret_cast<const float4*>(&g_p2[s1 * OUT_CH + q * 4]);
        float4 v2 = *reinterpret_cast<const float4*>(&g_p2[s2 * OUT_CH + q * 4]);
        float4 v3 = *reinterpret_cast<const float4*>(&g_p2[s3 * OUT_CH + q * 4]);
        sum.x += v0.x + v1.x + v2.x + v3.x;
        sum.y += v0.y + v1.y + v2.y + v3.y;
        sum.z += v0.z + v1.z + v2.z + v3.z;
        sum.w += v0.w + v1.w + v2.w + v3.w;
    }
    for (; j < end; j++) {
        int s = g_csr[j];
        float4 v = *reinterpret_cast<const float4*>(&g_p2[s * OUT_CH + q * 4]);
        sum.x += v.x; sum.y += v.y; sum.z += v.z; sum.w += v.w;
    }

    float inv_d = 1.0f / fmaxf((float)deg, 1.0f);
    float4 r = *reinterpret_cast<const float4*>(&g_r2[n * OUT_CH + q * 4]);
    float4 o;
    o.x = sum.x * inv_d + r.x;
    o.y = sum.y * inv_d + r.y;
    o.z = sum.z * inv_d + r.z;
    o.w = sum.w * inv_d + r.w;
    *reinterpret_cast<float4*>(&out[n * OUT_CH + q * 4]) = o;
}

extern "C" void kernel_launch(void* const* d_in, const int* in_sizes, int n_in,
                              void* d_out, int out_size) {
    const float* x   = (const float*)d_in[0];
    const float* W1l = (const float*)d_in[1];
    const float* W1r = (const float*)d_in[2];
    const float* b1  = (const float*)d_in[3];
    const float* W2l = (const float*)d_in[4];
    const float* W2r = (const float*)d_in[5];
    const float* b2  = (const float*)d_in[6];
    const int*   ei  = (const int*)d_in[7];

    int n_nodes = in_sizes[0] / IN_CH;
    int n_edges = in_sizes[7] / 2;
    if (n_nodes > N_NODES_MAX) n_nodes = N_NODES_MAX;
    if (n_edges > N_EDGES_MAX) n_edges = N_EDGES_MAX;

    const int B = 256;
    int egrid = (n_edges + B - 1) / B;

    init_kernel<<<(n_nodes + B - 1) / B, B>>>(ei, in_sizes[7], n_nodes);
    count_kernel<<<egrid, B>>>(ei, n_edges, n_nodes);
    scan_kernel<<<1, SCAN_THREADS>>>(n_nodes);
    build_kernel<<<egrid, B>>>(ei, n_edges, n_nodes);

    gemm1_kernel<<<(n_nodes * 4 + B - 1) / B, B>>>(x, W1l, W1r, b1, n_nodes);
    gather1_layer2_kernel<<<(n_nodes * 4 + B - 1) / B, B>>>(W2l, W2r, b2, n_nodes);
    gather2_combine_kernel<<<(n_nodes * 2 + B - 1) / B, B>>>((float*)d_out, n_nodes);
}

// round 5
// speedup vs baseline: 1.6985x; 1.6985x over previous
#include <cuda_runtime.h>

#define N_NODES_MAX 50000
#define N_EDGES_MAX 800000
#define IN_CH 64
#define HIDDEN 16
#define OUT_CH 8

// Scratch (allocation-free rule: __device__ globals)
__device__ int   g_is64;
__device__ float g_deg[N_NODES_MAX];
__device__ float g_p1[N_NODES_MAX * HIDDEN];
__device__ float g_r1[N_NODES_MAX * HIDDEN];
__device__ float g_s1[N_NODES_MAX * HIDDEN];
__device__ float g_p2[N_NODES_MAX * OUT_CH];
__device__ float g_r2[N_NODES_MAX * OUT_CH];
__device__ float g_s2[N_NODES_MAX * OUT_CH];

// Vectorized global reduction (sm_90+): one L2 op for 4 floats.
__device__ __forceinline__ void red_add_v4(float* addr, float4 v) {
    asm volatile("red.global.add.v4.f32 [%0], {%1, %2, %3, %4};"
                 :: "l"(addr), "f"(v.x), "f"(v.y), "f"(v.z), "f"(v.w)
                 : "memory");
}

// Decode one edge from raw buffer (int64 or int32 little-endian).
__device__ __forceinline__ void load_edge(const int* __restrict__ ei, int e,
                                          int n_edges, int& src, int& dst) {
    if (g_is64) {
        const int2* p = reinterpret_cast<const int2*>(ei);
        src = p[e].x;
        dst = p[n_edges + e].x;
    } else {
        src = ei[e];
        dst = ei[n_edges + e];
    }
}

// Zero degree + dtype detection.
// int64 little-endian with indices in [0,50000): every odd int32 word is 0.
// int32: odd words are random indices — all-zero over 512 samples impossible.
__global__ void init_kernel(const int* __restrict__ ei_raw, int n_words, int n_nodes) {
    int i = blockIdx.x * blockDim.x + threadIdx.x;
    if (i == 0) {
        int nz = 0;
        int lim = n_words < 1024 ? n_words : 1024;
        for (int w = 1; w < lim; w += 2) nz += (ei_raw[w] != 0);
        g_is64 = (nz == 0) ? 1 : 0;
    }
    if (i < n_nodes) g_deg[i] = 0.0f;
}

// p1 = x @ W1l^T ; r1 = x @ W1r^T + b1 ; s1 = 0
// 4 threads per node; thread quarter q computes hidden channels [4q, 4q+4).
__global__ void gemm1_kernel(const float* __restrict__ x,
                             const float* __restrict__ W1l,
                             const float* __restrict__ W1r,
                             const float* __restrict__ b1,
                             int n_nodes) {
    __shared__ float sWl[HIDDEN * IN_CH];
    __shared__ float sWr[HIDDEN * IN_CH];
    __shared__ float sb[HIDDEN];
    for (int i = threadIdx.x; i < HIDDEN * IN_CH; i += blockDim.x) {
        sWl[i] = W1l[i];
        sWr[i] = W1r[i];
    }
    if (threadIdx.x < HIDDEN) sb[threadIdx.x] = b1[threadIdx.x];
    __syncthreads();

    int idx = blockIdx.x * blockDim.x + threadIdx.x;
    int n = idx >> 2;
    int q = idx & 3;
    if (n >= n_nodes) return;
    int h0 = q * 4;

    float accl[4], accr[4];
#pragma unroll
    for (int j = 0; j < 4; j++) { accl[j] = 0.0f; accr[j] = sb[h0 + j]; }

    const float4* xr = reinterpret_cast<const float4*>(x + (size_t)n * IN_CH);
#pragma unroll
    for (int c4 = 0; c4 < IN_CH / 4; c4++) {
        float4 v = xr[c4];
#pragma unroll
        for (int j = 0; j < 4; j++) {
            const float* wl = &sWl[(h0 + j) * IN_CH + c4 * 4];
            const float* wr = &sWr[(h0 + j) * IN_CH + c4 * 4];
            accl[j] += v.x * wl[0] + v.y * wl[1] + v.z * wl[2] + v.w * wl[3];
            accr[j] += v.x * wr[0] + v.y * wr[1] + v.z * wr[2] + v.w * wr[3];
        }
    }
    *reinterpret_cast<float4*>(&g_p1[n * HIDDEN + h0]) =
        make_float4(accl[0], accl[1], accl[2], accl[3]);
    *reinterpret_cast<float4*>(&g_r1[n * HIDDEN + h0]) =
        make_float4(accr[0], accr[1], accr[2], accr[3]);
    *reinterpret_cast<float4*>(&g_s1[n * HIDDEN + h0]) =
        make_float4(0.f, 0.f, 0.f, 0.f);
}

// Layer-1 scatter: 2 threads per edge. Half h handles channels [8h, 8h+8)
// (2 v4 REDs). Half 0 also bumps the degree counter.
__global__ void scatter1_kernel(const int* __restrict__ ei, int n_edges, int n_nodes) {
    int idx = blockIdx.x * blockDim.x + threadIdx.x;
    int e = idx >> 1;
    int half = idx & 1;
    if (e >= n_edges) return;
    int src, dst;
    load_edge(ei, e, n_edges, src, dst);
    if ((unsigned)src >= (unsigned)n_nodes || (unsigned)dst >= (unsigned)n_nodes) return;
    if (half == 0) atomicAdd(&g_deg[dst], 1.0f);
    const float4* p = reinterpret_cast<const float4*>(&g_p1[src * HIDDEN + half * 8]);
    float* s = &g_s1[dst * HIDDEN + half * 8];
    red_add_v4(&s[0], p[0]);
    red_add_v4(&s[4], p[1]);
}

// Fused: h = relu(s1/max(deg,1) + r1); p2 = h@W2l^T; r2 = h@W2r^T + b2; s2 = 0.
// One thread per node.
__global__ void layer2_kernel(const float* __restrict__ W2l,
                              const float* __restrict__ W2r,
                              const float* __restrict__ b2,
                              int n_nodes) {
    __shared__ float sWl[OUT_CH * HIDDEN];
    __shared__ float sWr[OUT_CH * HIDDEN];
    __shared__ float sb[OUT_CH];
    for (int i = threadIdx.x; i < OUT_CH * HIDDEN; i += blockDim.x) {
        sWl[i] = W2l[i];
        sWr[i] = W2r[i];
    }
    if (threadIdx.x < OUT_CH) sb[threadIdx.x] = b2[threadIdx.x];
    __syncthreads();

    int n = blockIdx.x * blockDim.x + threadIdx.x;
    if (n >= n_nodes) return;

    float inv_d = 1.0f / fmaxf(g_deg[n], 1.0f);
    float h[HIDDEN];
    const float4* s1 = reinterpret_cast<const float4*>(&g_s1[n * HIDDEN]);
    const float4* r1 = reinterpret_cast<const float4*>(&g_r1[n * HIDDEN]);
#pragma unroll
    for (int q = 0; q < HIDDEN / 4; q++) {
        float4 sv = s1[q];
        float4 rv = r1[q];
        h[q * 4 + 0] = fmaxf(sv.x * inv_d + rv.x, 0.0f);
        h[q * 4 + 1] = fmaxf(sv.y * inv_d + rv.y, 0.0f);
        h[q * 4 + 2] = fmaxf(sv.z * inv_d + rv.z, 0.0f);
        h[q * 4 + 3] = fmaxf(sv.w * inv_d + rv.w, 0.0f);
    }

    float accl[OUT_CH], accr[OUT_CH];
#pragma unroll
    for (int o = 0; o < OUT_CH; o++) { accl[o] = 0.0f; accr[o] = sb[o]; }
#pragma unroll
    for (int c = 0; c < HIDDEN; c++) {
        float v = h[c];
#pragma unroll
        for (int o = 0; o < OUT_CH; o++) {
            accl[o] += v * sWl[o * HIDDEN + c];
            accr[o] += v * sWr[o * HIDDEN + c];
        }
    }
    float4* p2o = reinterpret_cast<float4*>(&g_p2[n * OUT_CH]);
    float4* r2o = reinterpret_cast<float4*>(&g_r2[n * OUT_CH]);
    float4* s2o = reinterpret_cast<float4*>(&g_s2[n * OUT_CH]);
    p2o[0] = make_float4(accl[0], accl[1], accl[2], accl[3]);
    p2o[1] = make_float4(accl[4], accl[5], accl[6], accl[7]);
    r2o[0] = make_float4(accr[0], accr[1], accr[2], accr[3]);
    r2o[1] = make_float4(accr[4], accr[5], accr[6], accr[7]);
    s2o[0] = make_float4(0.f, 0.f, 0.f, 0.f);
    s2o[1] = make_float4(0.f, 0.f, 0.f, 0.f);
}

// Layer-2 scatter: 2 threads per edge, one v4 RED each.
__global__ void scatter2_kernel(const int* __restrict__ ei, int n_edges, int n_nodes) {
    int idx = blockIdx.x * blockDim.x + threadIdx.x;
    int e = idx >> 1;
    int half = idx & 1;
    if (e >= n_edges) return;
    int src, dst;
    load_edge(ei, e, n_edges, src, dst);
    if ((unsigned)src >= (unsigned)n_nodes || (unsigned)dst >= (unsigned)n_nodes) return;
    float4 v = *reinterpret_cast<const float4*>(&g_p2[src * OUT_CH + half * 4]);
    red_add_v4(&g_s2[dst * OUT_CH + half * 4], v);
}

// out = s2 / max(deg,1) + r2. 2 threads per node (float4 each).
__global__ void combine2_kernel(float* __restrict__ out, int n_nodes) {
    int idx = blockIdx.x * blockDim.x + threadIdx.x;
    int n = idx >> 1;
    int q = idx & 1;
    if (n >= n_nodes) return;
    float inv_d = 1.0f / fmaxf(g_deg[n], 1.0f);
    float4 s = *reinterpret_cast<const float4*>(&g_s2[n * OUT_CH + q * 4]);
    float4 r = *reinterpret_cast<const float4*>(&g_r2[n * OUT_CH + q * 4]);
    float4 o;
    o.x = s.x * inv_d + r.x;
    o.y = s.y * inv_d + r.y;
    o.z = s.z * inv_d + r.z;
    o.w = s.w * inv_d + r.w;
    *reinterpret_cast<float4*>(&out[n * OUT_CH + q * 4]) = o;
}

extern "C" void kernel_launch(void* const* d_in, const int* in_sizes, int n_in,
                              void* d_out, int out_size) {
    const float* x   = (const float*)d_in[0];
    const float* W1l = (const float*)d_in[1];
    const float* W1r = (const float*)d_in[2];
    const float* b1  = (const float*)d_in[3];
    const float* W2l = (const float*)d_in[4];
    const float* W2r = (const float*)d_in[5];
    const float* b2  = (const float*)d_in[6];
    const int*   ei  = (const int*)d_in[7];

    int n_nodes = in_sizes[0] / IN_CH;
    int n_edges = in_sizes[7] / 2;
    if (n_nodes > N_NODES_MAX) n_nodes = N_NODES_MAX;
    if (n_edges > N_EDGES_MAX) n_edges = N_EDGES_MAX;

    const int B = 256;

    init_kernel<<<(n_nodes + B - 1) / B, B>>>(ei, in_sizes[7], n_nodes);
    gemm1_kernel<<<(n_nodes * 4 + B - 1) / B, B>>>(x, W1l, W1r, b1, n_nodes);
    scatter1_kernel<<<(n_edges * 2 + B - 1) / B, B>>>(ei, n_edges, n_nodes);
    layer2_kernel<<<(n_nodes + B - 1) / B, B>>>(W2l, W2r, b2, n_nodes);
    scatter2_kernel<<<(n_edges * 2 + B - 1) / B, B>>>(ei, n_edges, n_nodes);
    combine2_kernel<<<(n_nodes * 2 + B - 1) / B, B>>>((float*)d_out, n_nodes);
}